// round 9
// baseline (speedup 1.0000x reference)
#include <cuda_runtime.h>
#include <math.h>
#include <cstdint>

// B=128, L=8192, NF=16, D=256, NC=4; bins k={23,68,137,273}
// d_in[0] input_sequence (B,L,NF) f32  -- only channel 0 used
// d_in[1] hidden_states UNUSED; d_in[2] cycle_weights; d_in[3] proj_w (D,8); d_in[4] proj_b
//
// Strategy: the stride-64B channel-0 gather is L1tex-wavefront-bound via LDG
// (16 wavefronts per warp-load, ceiling ~7.5TB/s at NAT clock). Bypass L1tex:
// cp.async.bulk (TMA engine) streams each batch row-block into SMEM
// (double-buffered, mbarrier-synced); threads read channel 0 from SMEM.

#define BB    128
#define LL    8192
#define NFF   16
#define DD    256
#define NCC   4
#define TPB   256
#define TROWS 256                    // rows per tile
#define TBYTES (TROWS * NFF * 4)     // 16384 B per tile
#define NTILES (LL / TROWS)          // 32

__device__ __forceinline__ uint32_t smem_u32(const void* p) {
    uint32_t a;
    asm("{ .reg .u64 t; cvta.to.shared.u64 t, %1; cvt.u32.u64 %0, t; }"
        : "=r"(a) : "l"(p));
    return a;
}

__global__ __launch_bounds__(TPB)
void cycle_detector_kernel(const float* __restrict__ seq,
                           const float* __restrict__ cw,
                           const float* __restrict__ pw,   // (D, 8) row-major
                           const float* __restrict__ pb,
                           float* __restrict__ out)
{
    __shared__ __align__(16) float buf[2][TROWS * NFF];   // 2 x 16KB
    __shared__ __align__(8) uint64_t mbar[2];
    __shared__ float sred[8][8];
    __shared__ float fwsh[8];

    const int b   = blockIdx.x;
    const int tid = threadIdx.x;

    const uint32_t mb0 = smem_u32(&mbar[0]);
    const uint32_t mb1 = smem_u32(&mbar[1]);

    if (tid == 0) {
        asm volatile("mbarrier.init.shared.b64 [%0], 1;" :: "r"(mb0) : "memory");
        asm volatile("mbarrier.init.shared.b64 [%0], 1;" :: "r"(mb1) : "memory");
    }
    __syncthreads();

    const char* src_base = (const char*)(seq + (size_t)b * (size_t)(LL * NFF));

    // prologue: issue tile 0 into buf 0
    if (tid == 0) {
        asm volatile("mbarrier.arrive.expect_tx.shared.b64 _, [%0], %1;"
                     :: "r"(mb0), "r"((uint32_t)TBYTES) : "memory");
        asm volatile("cp.async.bulk.shared::cta.global.mbarrier::complete_tx::bytes"
                     " [%0], [%1], %2, [%3];"
                     :: "r"(smem_u32(&buf[0][0])), "l"(src_base),
                        "r"((uint32_t)TBYTES), "r"(mb0) : "memory");
    }

    // twiddles: start angle for row tid, step +TROWS per tile
    const int KIDX[NCC] = {23, 68, 137, 273};
    const float TWO_PI = 6.28318530717958647692f;
    float re[NCC], im[NCC], cr[NCC], ci[NCC], dr[NCC], di[NCC];
#pragma unroll
    for (int j = 0; j < NCC; j++) {
        re[j] = 0.0f; im[j] = 0.0f;
        int m0 = (KIDX[j] * tid) & (LL - 1);
        float th0 = -TWO_PI * (float)m0 * (1.0f / (float)LL);
        sincosf(th0, &ci[j], &cr[j]);
        int md = (KIDX[j] * TROWS) & (LL - 1);
        float thd = -TWO_PI * (float)md * (1.0f / (float)LL);
        sincosf(thd, &di[j], &dr[j]);
    }

    for (int t = 0; t < NTILES; t++) {
        const int cur = t & 1;
        const uint32_t mb_cur = cur ? mb1 : mb0;

        // issue next tile into the other buffer (processed & synced at t-1)
        if (tid == 0 && t + 1 < NTILES) {
            const int nxt = (t + 1) & 1;
            const uint32_t mb_nxt = nxt ? mb1 : mb0;
            asm volatile("mbarrier.arrive.expect_tx.shared.b64 _, [%0], %1;"
                         :: "r"(mb_nxt), "r"((uint32_t)TBYTES) : "memory");
            asm volatile("cp.async.bulk.shared::cta.global.mbarrier::complete_tx::bytes"
                         " [%0], [%1], %2, [%3];"
                         :: "r"(smem_u32(&buf[nxt][0])),
                            "l"(src_base + (size_t)(t + 1) * TBYTES),
                            "r"((uint32_t)TBYTES), "r"(mb_cur * 0 + (nxt ? mb1 : mb0)) : "memory");
        }

        // wait current tile (phase = (t>>1)&1 for this buffer)
        {
            uint32_t parity = (uint32_t)((t >> 1) & 1);
            uint32_t done;
            asm volatile(
                "{\n\t.reg .pred p;\n\t"
                "mbarrier.try_wait.parity.acquire.cta.shared::cta.b64 p, [%1], %2;\n\t"
                "selp.b32 %0, 1, 0, p;\n\t}"
                : "=r"(done) : "r"(mb_cur), "r"(parity) : "memory");
            if (!done) {
                asm volatile(
                    "{\n\t.reg .pred P1;\n\t"
                    "W%=:\n\t"
                    "mbarrier.try_wait.parity.acquire.cta.shared::cta.b64 P1, [%0], %1, 0x989680;\n\t"
                    "@P1 bra.uni D%=;\n\t"
                    "bra.uni W%=;\n\t"
                    "D%=:\n\t}"
                    :: "r"(mb_cur), "r"(parity) : "memory");
            }
        }

        // process: thread tid handles global row t*TROWS + tid, channel 0
        float x = buf[cur][tid * NFF];
#pragma unroll
        for (int j = 0; j < NCC; j++) {
            re[j] = fmaf(x, cr[j], re[j]);
            im[j] = fmaf(x, ci[j], im[j]);
            float cn = cr[j] * dr[j] - ci[j] * di[j];
            ci[j]    = fmaf(ci[j], dr[j], cr[j] * di[j]);
            cr[j]    = cn;
        }

        __syncthreads();   // all done with buf[cur] before it is refilled at t+2
    }

    // ---- warp reduction ----
#pragma unroll
    for (int off = 16; off > 0; off >>= 1) {
#pragma unroll
        for (int j = 0; j < NCC; j++) {
            re[j] += __shfl_xor_sync(0xffffffffu, re[j], off);
            im[j] += __shfl_xor_sync(0xffffffffu, im[j], off);
        }
    }

    const int wid  = tid >> 5;
    const int lane = tid & 31;
    if (lane == 0) {
#pragma unroll
        for (int j = 0; j < NCC; j++) {
            sred[wid][j]     = re[j];
            sred[wid][4 + j] = im[j];
        }
    }
    __syncthreads();

    if (tid < 8) {
        float v = 0.0f;
#pragma unroll
        for (int w = 0; w < 8; w++) v += sred[w][tid];
        sred[0][tid] = v;
    }
    __syncthreads();

    if (tid < NCC) {
        float R = sred[0][tid];
        float I = sred[0][4 + tid];
        float mag = sqrtf(fmaf(R, R, I * I));
        float ph  = atan2f(I, R);
        float w   = cw[tid];
        fwsh[2 * tid]     = mag * w;
        fwsh[2 * tid + 1] = ph * w;
    }
    __syncthreads();

    float acc = pb[tid];
    const float* pwrow = pw + tid * (2 * NCC);
#pragma unroll
    for (int j = 0; j < 2 * NCC; j++)
        acc = fmaf(fwsh[j], pwrow[j], acc);
    out[b * DD + tid] = acc;
}

extern "C" void kernel_launch(void* const* d_in, const int* in_sizes, int n_in,
                              void* d_out, int out_size)
{
    const float* seq = (const float*)d_in[0];
    const float* cw  = (const float*)d_in[2];
    const float* pw  = (const float*)d_in[3];
    const float* pb  = (const float*)d_in[4];
    float* out       = (float*)d_out;

    cycle_detector_kernel<<<BB, TPB>>>(seq, cw, pw, pb, out);
}

// round 10
// speedup vs baseline: 1.4331x; 1.4331x over previous
#include <cuda_runtime.h>
#include <math.h>

// Problem constants (fixed by the dataset):
//   B=128, L=8192, NF=16, D=256, NC=4
//   FFT bins for CYCLES [1/12,1/4,1/2,1] @ SR=1/30, L=8192: k={23,68,137,273}
// Inputs (metadata order):
//   d_in[0] input_sequence (B,L,NF) f32   -- only channel 0 used
//   d_in[1] hidden_states  (B,L,D)  f32   -- UNUSED by reference; never read
//   d_in[2] cycle_weights  (NC,)    f32
//   d_in[3] proj_w         (D,2*NC) f32
//   d_in[4] proj_b         (D,)     f32
// Output: (B,D) f32
//
// Roofline: channel 0 sits at stride 64B; the DRAM atom is 64B, so mandatory
// traffic = B*L*64B = 67MB. Best measured = 67MB/8.93us = 7.5TB/s (~94% of
// effective HBM3e bandwidth for a 64B-granule stream). Measured dead ends:
// __ldcs (no traffic change, slight loss), split-2 grid=256 (no gain),
// occupancy 80% (no gain), cp.async.bulk double-buffer (loss). This config
// (TPB=1024, grid=128, front-batched loads) had the best profile-clock
// duration of all rounds.

#define BB   128
#define LL   8192
#define NFF  16
#define DD   256
#define NCC  4
#define TPB  1024
#define ITER (LL / TPB)   // 8

__global__ __launch_bounds__(TPB)
void cycle_detector_kernel(const float* __restrict__ seq,
                           const float* __restrict__ cw,
                           const float* __restrict__ pw,   // (D, 8) row-major
                           const float* __restrict__ pb,
                           float* __restrict__ out)
{
    const int b   = blockIdx.x;
    const int tid = threadIdx.x;

    const int KIDX[NCC] = {23, 68, 137, 273};
    const float TWO_PI = 6.28318530717958647692f;

    // ---- batch all 8 strided loads up front (max MLP) ----
    const float* base = seq + (size_t)b * (size_t)(LL * NFF) + (size_t)tid * NFF;
    float x[ITER];
#pragma unroll
    for (int i = 0; i < ITER; i++)
        x[i] = __ldg(base + (size_t)i * (TPB * NFF));

    // ---- twiddles: start angle for t=tid, step for t+=TPB ----
    float re[NCC], im[NCC];
    float cr[NCC], ci[NCC];
    float dr[NCC], di[NCC];
#pragma unroll
    for (int j = 0; j < NCC; j++) {
        re[j] = 0.0f; im[j] = 0.0f;
        int m0 = (KIDX[j] * tid) & (LL - 1);
        float th0 = -TWO_PI * (float)m0 * (1.0f / (float)LL);
        sincosf(th0, &ci[j], &cr[j]);
        int md = (KIDX[j] * TPB) & (LL - 1);
        float thd = -TWO_PI * (float)md * (1.0f / (float)LL);
        sincosf(thd, &di[j], &dr[j]);
    }

#pragma unroll
    for (int i = 0; i < ITER; i++) {
#pragma unroll
        for (int j = 0; j < NCC; j++) {
            re[j] = fmaf(x[i], cr[j], re[j]);
            im[j] = fmaf(x[i], ci[j], im[j]);
            float cn = cr[j] * dr[j] - ci[j] * di[j];
            ci[j]    = fmaf(ci[j], dr[j], cr[j] * di[j]);
            cr[j]    = cn;
        }
    }

    // ---- warp reduction ----
#pragma unroll
    for (int off = 16; off > 0; off >>= 1) {
#pragma unroll
        for (int j = 0; j < NCC; j++) {
            re[j] += __shfl_xor_sync(0xffffffffu, re[j], off);
            im[j] += __shfl_xor_sync(0xffffffffu, im[j], off);
        }
    }

    __shared__ float sred[32][8];   // [warp][re0..3, im0..3]
    __shared__ float fwsh[8];       // weighted features (mag,phase interleaved)

    const int wid  = tid >> 5;
    const int lane = tid & 31;
    if (lane == 0) {
#pragma unroll
        for (int j = 0; j < NCC; j++) {
            sred[wid][j]     = re[j];
            sred[wid][4 + j] = im[j];
        }
    }
    __syncthreads();

    if (tid < 8) {
        float v = 0.0f;
#pragma unroll
        for (int w = 0; w < 32; w++) v += sred[w][tid];
        sred[0][tid] = v;   // final bin sums live in row 0
    }
    __syncthreads();

    if (tid < NCC) {
        float R = sred[0][tid];
        float I = sred[0][4 + tid];
        float mag = sqrtf(fmaf(R, R, I * I));
        float ph  = atan2f(I, R);
        float w   = cw[tid];
        fwsh[2 * tid]     = mag * w;
        fwsh[2 * tid + 1] = ph * w;
    }
    __syncthreads();

    // ---- projection: out[b,d] = pb[d] + sum_j fwsh[j] * pw[d*8+j] ----
    if (tid < DD) {
        float acc = pb[tid];
        const float* pwrow = pw + tid * (2 * NCC);
#pragma unroll
        for (int j = 0; j < 2 * NCC; j++)
            acc = fmaf(fwsh[j], pwrow[j], acc);
        out[b * DD + tid] = acc;
    }
}

extern "C" void kernel_launch(void* const* d_in, const int* in_sizes, int n_in,
                              void* d_out, int out_size)
{
    const float* seq = (const float*)d_in[0];
    // d_in[1] = hidden_states: intentionally unused (reference never reads it)
    const float* cw  = (const float*)d_in[2];
    const float* pw  = (const float*)d_in[3];
    const float* pb  = (const float*)d_in[4];
    float* out       = (float*)d_out;

    cycle_detector_kernel<<<BB, TPB>>>(seq, cw, pw, pb, out);
}